// round 6
// baseline (speedup 1.0000x reference)
#include <cuda_runtime.h>
#include <cstdint>

constexpr int B_ = 64, C_ = 512, NE_ = 80, NI_ = 20, E_ = 512;
#define DTC 0.1f

constexpr size_t OFF_RI = (size_t)B_ * C_ * NE_;
constexpr size_t OFF_VE = OFF_RI + (size_t)B_ * C_ * NI_;
constexpr size_t OFF_VI = OFF_VE + (size_t)B_ * C_ * NE_;

// ---------------- helpers ----------------
__device__ __forceinline__ float2 ldg2(const float* p) {
    return __ldg((const float2*)p);
}
__device__ __forceinline__ float2 add2(float2 a, float2 b) {
    return make_float2(a.x + b.x, a.y + b.y);
}
__device__ __forceinline__ float2 neg2(float2 a) {
    return make_float2(-a.x, -a.y);
}
__device__ __forceinline__ uint32_t bfx2(float2 f) {
    uint32_t r;
    asm("cvt.rn.bf16x2.f32 %0, %1, %2;" : "=r"(r) : "f"(f.y), "f"(f.x));
    return r;
}
__device__ __forceinline__ void mma16(float d[4], uint32_t a0, uint32_t a1,
                                      uint32_t a2, uint32_t a3,
                                      uint32_t b0, uint32_t b1) {
    asm("mma.sync.aligned.m16n8k16.row.col.f32.bf16.bf16.f32 "
        "{%0,%1,%2,%3}, {%4,%5,%6,%7}, {%8,%9}, {%0,%1,%2,%3};"
        : "+f"(d[0]), "+f"(d[1]), "+f"(d[2]), "+f"(d[3])
        : "r"(a0), "r"(a1), "r"(a2), "r"(a3), "r"(b0), "r"(b1));
}

// Warp layout: 8 warps; wm = w>>1 in 0..3 -> M rows [wm*16, wm*16+16);
// wn = w&1 -> N cols [wn*40, wn*40+40). Fragment: lm = lane>>2 (row-in-8),
// lc = lane&3 (k-pair). No shared memory, no barriers: fragments fed by
// LDG.64 straight from gmem; L1 (full 228KB) handles intra-CTA reuse.
__global__ void __launch_bounds__(256, 3)
ei_direct(const float* __restrict__ thal, const float* __restrict__ thal_inc,
          const float* __restrict__ l23_fb, const float* __restrict__ r_e,
          const float* __restrict__ r_i, const float* __restrict__ e_v,
          const float* __restrict__ i_v, const float* __restrict__ input_proj,
          const float* __restrict__ feedback_proj, const float* __restrict__ W_ee,
          const float* __restrict__ W_ei, const float* __restrict__ W_ie,
          float* __restrict__ out) {
    const int t = threadIdx.x, c = blockIdx.x;
    const int w = t >> 5, lane = t & 31;
    const int wm = w >> 1, wn = w & 1;
    const int lm = lane >> 2, lc = lane & 3;
    const int r0 = wm * 16 + lm, r1 = r0 + 8;

    float accE[5][4], accI[3][4];
#pragma unroll
    for (int j = 0; j < 5; j++)
#pragma unroll
        for (int q = 0; q < 4; q++) accE[j][q] = 0.f;
#pragma unroll
    for (int j = 0; j < 3; j++)
#pragma unroll
        for (int q = 0; q < 4; q++) accI[j][q] = 0.f;

    int rw[5];
#pragma unroll
    for (int j = 0; j < 5; j++) rw[j] = wn * 40 + j * 8 + lm;

    // ================= I_ext: (thal + thal_inc) @ input_proj^T, K=512 ========
    {
        const float* a0 = thal_inc + ((size_t)r0 * C_ + c) * E_ + 2 * lc;
        const float* a1 = thal_inc + ((size_t)r1 * C_ + c) * E_ + 2 * lc;
        const float* t0 = thal + (size_t)r0 * E_ + 2 * lc;
        const float* t1 = thal + (size_t)r1 * E_ + 2 * lc;
        const float* wb[5];
#pragma unroll
        for (int j = 0; j < 5; j++)
            wb[j] = input_proj + ((size_t)c * NE_ + rw[j]) * E_ + 2 * lc;
#pragma unroll 2
        for (int s = 0; s < 32; s++) {
            const int kb = s * 16;
            float2 f0 = add2(ldg2(a0 + kb),     ldg2(t0 + kb));
            float2 f1 = add2(ldg2(a1 + kb),     ldg2(t1 + kb));
            float2 f2 = add2(ldg2(a0 + kb + 8), ldg2(t0 + kb + 8));
            float2 f3 = add2(ldg2(a1 + kb + 8), ldg2(t1 + kb + 8));
            const uint32_t A0 = bfx2(f0), A1 = bfx2(f1), A2 = bfx2(f2), A3 = bfx2(f3);
#pragma unroll
            for (int j = 0; j < 5; j++) {
                uint32_t b0 = bfx2(ldg2(wb[j] + kb));
                uint32_t b1 = bfx2(ldg2(wb[j] + kb + 8));
                mma16(accE[j], A0, A1, A2, A3, b0, b1);
            }
        }
    }

    // ================= I_fb: l23_fb @ feedback_proj^T, K=80 ==================
    {
        const float* a0 = l23_fb + ((size_t)r0 * C_ + c) * NE_ + 2 * lc;
        const float* a1 = l23_fb + ((size_t)r1 * C_ + c) * NE_ + 2 * lc;
        const float* wb[5];
#pragma unroll
        for (int j = 0; j < 5; j++)
            wb[j] = feedback_proj + ((size_t)c * NE_ + rw[j]) * NE_ + 2 * lc;
#pragma unroll
        for (int s = 0; s < 5; s++) {
            const int kb = s * 16;
            const uint32_t A0 = bfx2(ldg2(a0 + kb));
            const uint32_t A1 = bfx2(ldg2(a1 + kb));
            const uint32_t A2 = bfx2(ldg2(a0 + kb + 8));
            const uint32_t A3 = bfx2(ldg2(a1 + kb + 8));
#pragma unroll
            for (int j = 0; j < 5; j++) {
                uint32_t b0 = bfx2(ldg2(wb[j] + kb));
                uint32_t b1 = bfx2(ldg2(wb[j] + kb + 8));
                mma16(accE[j], A0, A1, A2, A3, b0, b1);
            }
        }
    }

    // ================= I_ee (accE) + I_ei (accI): r_e shared A, K=80 =========
    {
        const float* a0 = r_e + ((size_t)r0 * C_ + c) * NE_ + 2 * lc;
        const float* a1 = r_e + ((size_t)r1 * C_ + c) * NE_ + 2 * lc;
        const float* wb[5];
#pragma unroll
        for (int j = 0; j < 5; j++)
            wb[j] = W_ee + ((size_t)c * NE_ + rw[j]) * NE_ + 2 * lc;
        const float* wi[3];
        bool wiv[3];
#pragma unroll
        for (int j = 0; j < 3; j++) {
            const int rr = j * 8 + lm;
            wiv[j] = (rr < NI_);
            wi[j] = W_ei + ((size_t)c * NI_ + (wiv[j] ? rr : 0)) * NE_ + 2 * lc;
        }
        const float2 z = make_float2(0.f, 0.f);
#pragma unroll
        for (int s = 0; s < 5; s++) {
            const int kb = s * 16;
            const uint32_t A0 = bfx2(ldg2(a0 + kb));
            const uint32_t A1 = bfx2(ldg2(a1 + kb));
            const uint32_t A2 = bfx2(ldg2(a0 + kb + 8));
            const uint32_t A3 = bfx2(ldg2(a1 + kb + 8));
#pragma unroll
            for (int j = 0; j < 5; j++) {
                uint32_t b0 = bfx2(ldg2(wb[j] + kb));
                uint32_t b1 = bfx2(ldg2(wb[j] + kb + 8));
                mma16(accE[j], A0, A1, A2, A3, b0, b1);
            }
            if (wn == 0) {
#pragma unroll
                for (int j = 0; j < 3; j++) {
                    uint32_t b0 = bfx2(wiv[j] ? ldg2(wi[j] + kb) : z);
                    uint32_t b1 = bfx2(wiv[j] ? ldg2(wi[j] + kb + 8) : z);
                    mma16(accI[j], A0, A1, A2, A3, b0, b1);
                }
            }
        }
    }

    // ================= I_ie: -(r_i @ W_ie^T), K=20 ===========================
    {
        const float* a0 = r_i + ((size_t)r0 * C_ + c) * NI_ + 2 * lc;
        const float* a1 = r_i + ((size_t)r1 * C_ + c) * NI_ + 2 * lc;
        const float* wb[5];
#pragma unroll
        for (int j = 0; j < 5; j++)
            wb[j] = W_ie + ((size_t)c * NE_ + rw[j]) * NI_ + 2 * lc;
        const float2 z = make_float2(0.f, 0.f);
        // step 0: cols 0..15 (full)
        {
            const uint32_t A0 = bfx2(neg2(ldg2(a0)));
            const uint32_t A1 = bfx2(neg2(ldg2(a1)));
            const uint32_t A2 = bfx2(neg2(ldg2(a0 + 8)));
            const uint32_t A3 = bfx2(neg2(ldg2(a1 + 8)));
#pragma unroll
            for (int j = 0; j < 5; j++) {
                uint32_t b0 = bfx2(ldg2(wb[j]));
                uint32_t b1 = bfx2(ldg2(wb[j] + 8));
                mma16(accE[j], A0, A1, A2, A3, b0, b1);
            }
        }
        // step 1: cols 16..19 valid (lc < 2), rest zero
        {
            const bool v = (lc < 2);
            const uint32_t A0 = bfx2(v ? neg2(ldg2(a0 + 16)) : z);
            const uint32_t A1 = bfx2(v ? neg2(ldg2(a1 + 16)) : z);
            const uint32_t Z = bfx2(z);
#pragma unroll
            for (int j = 0; j < 5; j++) {
                uint32_t b0 = bfx2(v ? ldg2(wb[j] + 16) : z);
                mma16(accE[j], A0, A1, Z, Z, b0, Z);
            }
        }
    }

    // ================= epilogue: leaky integration + relu ====================
#pragma unroll
    for (int j = 0; j < 5; j++) {
        const int col = wn * 40 + j * 8 + 2 * lc;
        const size_t i0 = ((size_t)r0 * C_ + c) * NE_ + col;
        const size_t i1 = ((size_t)r1 * C_ + c) * NE_ + col;
        float2 ev0 = *(const float2*)(e_v + i0);
        float2 ev1 = *(const float2*)(e_v + i1);
        float v0x = ev0.x + DTC * (accE[j][0] - ev0.x);
        float v0y = ev0.y + DTC * (accE[j][1] - ev0.y);
        float v1x = ev1.x + DTC * (accE[j][2] - ev1.x);
        float v1y = ev1.y + DTC * (accE[j][3] - ev1.y);
        *(float2*)(out + i0)          = make_float2(fmaxf(v0x, 0.f), fmaxf(v0y, 0.f));
        *(float2*)(out + i1)          = make_float2(fmaxf(v1x, 0.f), fmaxf(v1y, 0.f));
        *(float2*)(out + OFF_VE + i0) = make_float2(v0x, v0y);
        *(float2*)(out + OFF_VE + i1) = make_float2(v1x, v1y);
    }
    if (wn == 0) {
#pragma unroll
        for (int j = 0; j < 3; j++) {
            const int col = j * 8 + 2 * lc;
            if (col < NI_) {
                const size_t i0 = ((size_t)r0 * C_ + c) * NI_ + col;
                const size_t i1 = ((size_t)r1 * C_ + c) * NI_ + col;
                float2 iv0 = *(const float2*)(i_v + i0);
                float2 iv1 = *(const float2*)(i_v + i1);
                float v0x = iv0.x + DTC * (accI[j][0] - iv0.x);
                float v0y = iv0.y + DTC * (accI[j][1] - iv0.y);
                float v1x = iv1.x + DTC * (accI[j][2] - iv1.x);
                float v1y = iv1.y + DTC * (accI[j][3] - iv1.y);
                *(float2*)(out + OFF_RI + i0) = make_float2(fmaxf(v0x, 0.f), fmaxf(v0y, 0.f));
                *(float2*)(out + OFF_RI + i1) = make_float2(fmaxf(v1x, 0.f), fmaxf(v1y, 0.f));
                *(float2*)(out + OFF_VI + i0) = make_float2(v0x, v0y);
                *(float2*)(out + OFF_VI + i1) = make_float2(v1x, v1y);
            }
        }
    }
}

extern "C" void kernel_launch(void* const* d_in, const int* in_sizes, int n_in,
                              void* d_out, int out_size) {
    (void)in_sizes; (void)n_in; (void)out_size;
    ei_direct<<<C_, 256>>>(
        (const float*)d_in[0],   // thal
        (const float*)d_in[1],   // thal_increments
        (const float*)d_in[2],   // l23_fb
        (const float*)d_in[3],   // r_e
        (const float*)d_in[4],   // r_i
        (const float*)d_in[5],   // e_v
        (const float*)d_in[6],   // i_v
        (const float*)d_in[7],   // input_proj
        (const float*)d_in[8],   // feedback_proj
        (const float*)d_in[9],   // W_ee
        (const float*)d_in[10],  // W_ei
        (const float*)d_in[11],  // W_ie
        (float*)d_out);
}

// round 7
// speedup vs baseline: 1.7535x; 1.7535x over previous
#include <cuda_runtime.h>
#include <cstdint>

constexpr int B_ = 64, C_ = 512, NE_ = 80, NI_ = 20, E_ = 512;
#define DTC 0.1f

// stage tile: A [64 x 32] + W [80 x 32], row stride 40 floats (conflict-free
// for half-warp phased LDS.64 fragment reads and cp.async 16B stores).
constexpr int LDSW   = 40;
constexpr int A_F    = 64 * LDSW;          // 2560 floats
constexpr int W_F    = 80 * LDSW;          // 3200 floats
constexpr int STAGE_F = A_F + W_F;         // 5760 floats = 23040 B
constexpr int NSTAGE  = 3;
// persistent W_ei buffer: 20 rows x 88 stride (rows >=20 handled by predicate)
constexpr int LDWEI  = 88;
constexpr int WEI_OFF = NSTAGE * STAGE_F;          // 17280 floats
constexpr int WEI_F   = 20 * LDWEI;                // 1760 floats
constexpr int SMEM_BYTES = (WEI_OFF + WEI_F) * 4;  // 76160 B -> 3 CTAs/SM (with 1KB/CTA reserve)

constexpr size_t OFF_RI = (size_t)B_ * C_ * NE_;
constexpr size_t OFF_VE = OFF_RI + (size_t)B_ * C_ * NI_;
constexpr size_t OFF_VI = OFF_VE + (size_t)B_ * C_ * NE_;

// ---------------- helpers ----------------
__device__ __forceinline__ uint32_t s2u(const void* p) {
    uint32_t a;
    asm("{ .reg .u64 t; cvta.to.shared.u64 t, %1; cvt.u32.u64 %0, t; }" : "=r"(a) : "l"(p));
    return a;
}
__device__ __forceinline__ void cpa16(uint32_t dst, const float* src) {
    asm volatile("cp.async.cg.shared.global [%0], [%1], 16;" :: "r"(dst), "l"(src));
}
__device__ __forceinline__ void cpa16z(uint32_t dst, const float* src) {
    asm volatile("cp.async.cg.shared.global [%0], [%1], 16, 0;" :: "r"(dst), "l"(src));
}
#define CP_COMMIT() asm volatile("cp.async.commit_group;" ::: "memory")
#define CP_WAIT1()  asm volatile("cp.async.wait_group 1;" ::: "memory")
#define CP_WAIT0()  asm volatile("cp.async.wait_group 0;" ::: "memory")

__device__ __forceinline__ uint32_t bfx2(float2 f) {
    uint32_t r;
    asm("cvt.rn.bf16x2.f32 %0, %1, %2;" : "=r"(r) : "f"(f.y), "f"(f.x));
    return r;
}
__device__ __forceinline__ void mma16(float d[4], uint32_t a0, uint32_t a1,
                                      uint32_t a2, uint32_t a3,
                                      uint32_t b0, uint32_t b1) {
    asm("mma.sync.aligned.m16n8k16.row.col.f32.bf16.bf16.f32 "
        "{%0,%1,%2,%3}, {%4,%5,%6,%7}, {%8,%9}, {%0,%1,%2,%3};"
        : "+f"(d[0]), "+f"(d[1]), "+f"(d[2]), "+f"(d[3])
        : "r"(a0), "r"(a1), "r"(a2), "r"(a3), "r"(b0), "r"(b1));
}

// ---------------- chunk table ----------------
// ci 0-15 : I_ext  k0=ci*32           (A=thal_inc, W=input_proj), ksteps=2
// ci 16-18: I_fb   k0=(ci-16)*32      (A=l23_fb, W=feedback_proj), ksteps 2,2,1
// ci 19-21: I_ee   k0=(ci-19)*32      (A=r_e, W=W_ee), ksteps 2,2,1; +I_ei via Wei
// ci 22   : I_ie   K=20 pad 32        (A=r_i, W=W_ie, negated A), ksteps=2
__device__ __forceinline__ void prefetch(
    int ci, int c, int t, float* sm,
    const float* thal_inc, const float* l23_fb, const float* r_e,
    const float* r_i, const float* input_proj, const float* feedback_proj,
    const float* W_ee, const float* W_ei, const float* W_ie) {
    const int slot = ci % NSTAGE;
    const uint32_t asb = s2u(sm + slot * STAGE_F);
    const uint32_t wsb = asb + A_F * 4;

    if (ci < 16) {
        const int k0 = ci * 32;
        for (int idx = t; idx < 1152; idx += 256) {
            if (idx < 512) {
                int row = idx >> 3, g = idx & 7;
                cpa16(asb + (row * LDSW + g * 4) * 4,
                      thal_inc + ((size_t)row * C_ + c) * E_ + k0 + g * 4);
            } else {
                int j = idx - 512, row = j >> 3, g = j & 7;
                cpa16(wsb + (row * LDSW + g * 4) * 4,
                      input_proj + ((size_t)c * NE_ + row) * E_ + k0 + g * 4);
            }
        }
    } else if (ci == 16 || ci == 17 || ci == 19 || ci == 20) {
        const bool isB = ci < 19;
        const int k0 = (ci - (isB ? 16 : 19)) * 32;
        const float* Ap = isB ? l23_fb : r_e;
        const float* Wp = isB ? feedback_proj : W_ee;
        const int tot = (ci == 19) ? 1152 + 400 : 1152;
        const uint32_t weib = s2u(sm + WEI_OFF);
        for (int idx = t; idx < tot; idx += 256) {
            if (idx < 512) {
                int row = idx >> 3, g = idx & 7;
                cpa16(asb + (row * LDSW + g * 4) * 4,
                      Ap + ((size_t)row * C_ + c) * NE_ + k0 + g * 4);
            } else if (idx < 1152) {
                int j = idx - 512, row = j >> 3, g = j & 7;
                cpa16(wsb + (row * LDSW + g * 4) * 4,
                      Wp + ((size_t)c * NE_ + row) * NE_ + k0 + g * 4);
            } else {
                int j = idx - 1152, row = j / 20, g = j % 20;
                cpa16(weib + (row * LDWEI + g * 4) * 4,
                      W_ei + ((size_t)c * NI_ + row) * NE_ + g * 4);
            }
        }
    } else if (ci == 18 || ci == 21) {
        const bool isB = ci == 18;
        const float* Ap = isB ? l23_fb : r_e;
        const float* Wp = isB ? feedback_proj : W_ee;
        for (int idx = t; idx < 576; idx += 256) {
            if (idx < 256) {
                int row = idx >> 2, g = idx & 3;
                cpa16(asb + (row * LDSW + g * 4) * 4,
                      Ap + ((size_t)row * C_ + c) * NE_ + 64 + g * 4);
            } else {
                int j = idx - 256, row = j >> 2, g = j & 3;
                cpa16(wsb + (row * LDSW + g * 4) * 4,
                      Wp + ((size_t)c * NE_ + row) * NE_ + 64 + g * 4);
            }
        }
    } else {  // ci == 22
        for (int idx = t; idx < 1152; idx += 256) {
            if (idx < 512) {
                int row = idx >> 3, g = idx & 7;
                uint32_t dst = asb + (row * LDSW + g * 4) * 4;
                const float* src = r_i + ((size_t)row * C_ + c) * NI_;
                if (g < 5) cpa16(dst, src + g * 4); else cpa16z(dst, src);
            } else {
                int j = idx - 512, row = j >> 3, g = j & 7;
                uint32_t dst = wsb + (row * LDSW + g * 4) * 4;
                const float* src = W_ie + ((size_t)c * NE_ + row) * NI_;
                if (g < 5) cpa16(dst, src + g * 4); else cpa16z(dst, src);
            }
        }
    }
}

__global__ void __launch_bounds__(256, 3)
ei_bf16(const float* __restrict__ thal, const float* __restrict__ thal_inc,
        const float* __restrict__ l23_fb, const float* __restrict__ r_e,
        const float* __restrict__ r_i, const float* __restrict__ e_v,
        const float* __restrict__ i_v, const float* __restrict__ input_proj,
        const float* __restrict__ feedback_proj, const float* __restrict__ W_ee,
        const float* __restrict__ W_ei, const float* __restrict__ W_ie,
        float* __restrict__ out) {
    extern __shared__ float sm[];
    const int t = threadIdx.x, c = blockIdx.x;
    const int w = t >> 5, lane = t & 31;
    const int wm = w >> 1, wn = w & 1;
    const int m0 = wm * 16, lm = lane >> 2, lc = lane & 3;

    float accE[5][4], accI[3][4];
#pragma unroll
    for (int j = 0; j < 5; j++)
#pragma unroll
        for (int q = 0; q < 4; q++) accE[j][q] = 0.f;
#pragma unroll
    for (int j = 0; j < 3; j++)
#pragma unroll
        for (int q = 0; q < 4; q++) accI[j][q] = 0.f;

    prefetch(0, c, t, sm, thal_inc, l23_fb, r_e, r_i,
             input_proj, feedback_proj, W_ee, W_ei, W_ie);
    CP_COMMIT();
    prefetch(1, c, t, sm, thal_inc, l23_fb, r_e, r_i,
             input_proj, feedback_proj, W_ee, W_ei, W_ie);
    CP_COMMIT();

    const float* Wei = sm + WEI_OFF;
    const bool wiv2 = (lm < 4);   // W_ei row 16+lm valid only for lm<4

    for (int ci = 0; ci < 23; ci++) {
        if (ci == 22) CP_WAIT0(); else CP_WAIT1();
        __syncthreads();   // chunk ci visible to all; chunk ci-1 readers done
        if (ci + 2 <= 22) {
            prefetch(ci + 2, c, t, sm, thal_inc, l23_fb, r_e, r_i,
                     input_proj, feedback_proj, W_ee, W_ei, W_ie);
            CP_COMMIT();
        }

        const float* As = sm + (ci % NSTAGE) * STAGE_F;
        const float* Ws = As + A_F;
        const int ksteps = (ci == 18 || ci == 21) ? 1 : 2;
        const bool doI = (ci >= 19 && ci <= 21);
        const bool neg = (ci == 22);
        const int kei0 = (ci - 19) * 32;
        const float2 z = make_float2(0.f, 0.f);

#pragma unroll 2
        for (int ks = 0; ks < ksteps; ks++) {
            const int kb = ks * 16;
            const float* ap = As + (m0 + lm) * LDSW + kb + 2 * lc;
            float2 fa0 = *(const float2*)(ap);
            float2 fa1 = *(const float2*)(ap + 8 * LDSW);
            float2 fa2 = *(const float2*)(ap + 8);
            float2 fa3 = *(const float2*)(ap + 8 * LDSW + 8);
            if (ci < 16) {   // fold broadcast thal (L2-hot) into fragments
                const float* tp = thal + (size_t)(m0 + lm) * E_ + ci * 32 + kb + 2 * lc;
                float2 t00 = __ldg((const float2*)(tp));
                float2 t01 = __ldg((const float2*)(tp + 8));
                float2 t10 = __ldg((const float2*)(tp + 8 * E_));
                float2 t11 = __ldg((const float2*)(tp + 8 * E_ + 8));
                fa0.x += t00.x; fa0.y += t00.y; fa2.x += t01.x; fa2.y += t01.y;
                fa1.x += t10.x; fa1.y += t10.y; fa3.x += t11.x; fa3.y += t11.y;
            }
            if (neg) {
                fa0.x = -fa0.x; fa0.y = -fa0.y; fa1.x = -fa1.x; fa1.y = -fa1.y;
                fa2.x = -fa2.x; fa2.y = -fa2.y; fa3.x = -fa3.x; fa3.y = -fa3.y;
            }
            const uint32_t a0 = bfx2(fa0), a1 = bfx2(fa1), a2 = bfx2(fa2), a3 = bfx2(fa3);
#pragma unroll
            for (int j = 0; j < 5; j++) {
                const float* wp = Ws + (wn * 40 + j * 8 + lm) * LDSW + kb + 2 * lc;
                uint32_t b0 = bfx2(*(const float2*)(wp));
                uint32_t b1 = bfx2(*(const float2*)(wp + 8));
                mma16(accE[j], a0, a1, a2, a3, b0, b1);
            }
            if (doI && wn == 0) {
#pragma unroll
                for (int j = 0; j < 3; j++) {
                    const float* wp = Wei + (j * 8 + lm) * LDWEI + kei0 + kb + 2 * lc;
                    const bool v = (j < 2) || wiv2;
                    uint32_t b0 = bfx2(v ? *(const float2*)(wp) : z);
                    uint32_t b1 = bfx2(v ? *(const float2*)(wp + 8) : z);
                    mma16(accI[j], a0, a1, a2, a3, b0, b1);
                }
            }
        }
    }

    // ---------------- epilogue: leaky integration + relu ----------------
    const int r0 = m0 + lm, r1 = r0 + 8;
#pragma unroll
    for (int j = 0; j < 5; j++) {
        const int col = wn * 40 + j * 8 + 2 * lc;
        const size_t i0 = ((size_t)r0 * C_ + c) * NE_ + col;
        const size_t i1 = ((size_t)r1 * C_ + c) * NE_ + col;
        float2 ev0 = *(const float2*)(e_v + i0);
        float2 ev1 = *(const float2*)(e_v + i1);
        float v0x = ev0.x + DTC * (accE[j][0] - ev0.x);
        float v0y = ev0.y + DTC * (accE[j][1] - ev0.y);
        float v1x = ev1.x + DTC * (accE[j][2] - ev1.x);
        float v1y = ev1.y + DTC * (accE[j][3] - ev1.y);
        *(float2*)(out + i0)          = make_float2(fmaxf(v0x, 0.f), fmaxf(v0y, 0.f));
        *(float2*)(out + i1)          = make_float2(fmaxf(v1x, 0.f), fmaxf(v1y, 0.f));
        *(float2*)(out + OFF_VE + i0) = make_float2(v0x, v0y);
        *(float2*)(out + OFF_VE + i1) = make_float2(v1x, v1y);
    }
    if (wn == 0) {
#pragma unroll
        for (int j = 0; j < 3; j++) {
            const int col = j * 8 + 2 * lc;
            if (col < NI_) {
                const size_t i0 = ((size_t)r0 * C_ + c) * NI_ + col;
                const size_t i1 = ((size_t)r1 * C_ + c) * NI_ + col;
                float2 iv0 = *(const float2*)(i_v + i0);
                float2 iv1 = *(const float2*)(i_v + i1);
                float v0x = iv0.x + DTC * (accI[j][0] - iv0.x);
                float v0y = iv0.y + DTC * (accI[j][1] - iv0.y);
                float v1x = iv1.x + DTC * (accI[j][2] - iv1.x);
                float v1y = iv1.y + DTC * (accI[j][3] - iv1.y);
                *(float2*)(out + OFF_RI + i0) = make_float2(fmaxf(v0x, 0.f), fmaxf(v0y, 0.f));
                *(float2*)(out + OFF_RI + i1) = make_float2(fmaxf(v1x, 0.f), fmaxf(v1y, 0.f));
                *(float2*)(out + OFF_VI + i0) = make_float2(v0x, v0y);
                *(float2*)(out + OFF_VI + i1) = make_float2(v1x, v1y);
            }
        }
    }
}

extern "C" void kernel_launch(void* const* d_in, const int* in_sizes, int n_in,
                              void* d_out, int out_size) {
    (void)in_sizes; (void)n_in; (void)out_size;
    cudaFuncSetAttribute(ei_bf16, cudaFuncAttributeMaxDynamicSharedMemorySize,
                         SMEM_BYTES);
    ei_bf16<<<C_, 256, SMEM_BYTES>>>(
        (const float*)d_in[0],   // thal
        (const float*)d_in[1],   // thal_increments
        (const float*)d_in[2],   // l23_fb
        (const float*)d_in[3],   // r_e
        (const float*)d_in[4],   // r_i
        (const float*)d_in[5],   // e_v
        (const float*)d_in[6],   // i_v
        (const float*)d_in[7],   // input_proj
        (const float*)d_in[8],   // feedback_proj
        (const float*)d_in[9],   // W_ee
        (const float*)d_in[10],  // W_ei
        (const float*)d_in[11],  // W_ie
        (float*)d_out);
}

// round 8
// speedup vs baseline: 1.8325x; 1.0450x over previous
#include <cuda_runtime.h>
#include <cstdint>

constexpr int B_ = 64, C_ = 512, NE_ = 80, NI_ = 20, E_ = 512;
#define DTC 0.1f

// stage tile: A [64 x 32] + W [80 x 32], row stride 40 floats (conflict-free
// for half-warp phased LDS.64 fragment reads and cp.async 16B stores).
constexpr int LDSW   = 40;
constexpr int A_F    = 64 * LDSW;          // 2560 floats
constexpr int W_F    = 80 * LDSW;          // 3200 floats
constexpr int STAGE_F = A_F + W_F;         // 5760 floats = 23040 B
constexpr int NSTAGE  = 4;
// persistent W_ei buffer: 20 rows x 88 stride (rows >=20 handled by predicate)
constexpr int LDWEI  = 88;
constexpr int WEI_OFF = NSTAGE * STAGE_F;          // 23040 floats
constexpr int WEI_F   = 20 * LDWEI;                // 1760 floats
constexpr int SMEM_BYTES = (WEI_OFF + WEI_F) * 4;  // 99200 B -> 2 CTAs/SM

constexpr size_t OFF_RI = (size_t)B_ * C_ * NE_;
constexpr size_t OFF_VE = OFF_RI + (size_t)B_ * C_ * NI_;
constexpr size_t OFF_VI = OFF_VE + (size_t)B_ * C_ * NE_;

// ---------------- helpers ----------------
__device__ __forceinline__ uint32_t s2u(const void* p) {
    uint32_t a;
    asm("{ .reg .u64 t; cvta.to.shared.u64 t, %1; cvt.u32.u64 %0, t; }" : "=r"(a) : "l"(p));
    return a;
}
__device__ __forceinline__ void cpa16(uint32_t dst, const float* src) {
    asm volatile("cp.async.cg.shared.global [%0], [%1], 16;" :: "r"(dst), "l"(src));
}
__device__ __forceinline__ void cpa16z(uint32_t dst, const float* src) {
    asm volatile("cp.async.cg.shared.global [%0], [%1], 16, 0;" :: "r"(dst), "l"(src));
}
#define CP_COMMIT() asm volatile("cp.async.commit_group;" ::: "memory")
#define CP_WAIT2()  asm volatile("cp.async.wait_group 2;" ::: "memory")
#define CP_WAIT1()  asm volatile("cp.async.wait_group 1;" ::: "memory")
#define CP_WAIT0()  asm volatile("cp.async.wait_group 0;" ::: "memory")

__device__ __forceinline__ uint32_t bfx2(float2 f) {
    uint32_t r;
    asm("cvt.rn.bf16x2.f32 %0, %1, %2;" : "=r"(r) : "f"(f.y), "f"(f.x));
    return r;
}
__device__ __forceinline__ void mma16(float d[4], uint32_t a0, uint32_t a1,
                                      uint32_t a2, uint32_t a3,
                                      uint32_t b0, uint32_t b1) {
    asm("mma.sync.aligned.m16n8k16.row.col.f32.bf16.bf16.f32 "
        "{%0,%1,%2,%3}, {%4,%5,%6,%7}, {%8,%9}, {%0,%1,%2,%3};"
        : "+f"(d[0]), "+f"(d[1]), "+f"(d[2]), "+f"(d[3])
        : "r"(a0), "r"(a1), "r"(a2), "r"(a3), "r"(b0), "r"(b1));
}

// ---------------- chunk table ----------------
// ci 0-15 : I_ext  k0=ci*32           (A=thal_inc, W=input_proj), ksteps=2
// ci 16-18: I_fb   k0=(ci-16)*32      (A=l23_fb, W=feedback_proj), ksteps 2,2,1
// ci 19-21: I_ee   k0=(ci-19)*32      (A=r_e, W=W_ee), ksteps 2,2,1; +I_ei via Wei
// ci 22   : I_ie   K=20 pad 32        (A=r_i, W=W_ie, negated A), ksteps=2
__device__ __forceinline__ void prefetch(
    int ci, int c, int t, float* sm,
    const float* thal_inc, const float* l23_fb, const float* r_e,
    const float* r_i, const float* input_proj, const float* feedback_proj,
    const float* W_ee, const float* W_ei, const float* W_ie) {
    const int slot = ci % NSTAGE;
    const uint32_t asb = s2u(sm + slot * STAGE_F);
    const uint32_t wsb = asb + A_F * 4;

    if (ci < 16) {
        const int k0 = ci * 32;
        for (int idx = t; idx < 1152; idx += 256) {
            if (idx < 512) {
                int row = idx >> 3, g = idx & 7;
                cpa16(asb + (row * LDSW + g * 4) * 4,
                      thal_inc + ((size_t)row * C_ + c) * E_ + k0 + g * 4);
            } else {
                int j = idx - 512, row = j >> 3, g = j & 7;
                cpa16(wsb + (row * LDSW + g * 4) * 4,
                      input_proj + ((size_t)c * NE_ + row) * E_ + k0 + g * 4);
            }
        }
    } else if (ci == 16 || ci == 17 || ci == 19 || ci == 20) {
        const bool isB = ci < 19;
        const int k0 = (ci - (isB ? 16 : 19)) * 32;
        const float* Ap = isB ? l23_fb : r_e;
        const float* Wp = isB ? feedback_proj : W_ee;
        const int tot = (ci == 19) ? 1152 + 400 : 1152;
        const uint32_t weib = s2u(sm + WEI_OFF);
        for (int idx = t; idx < tot; idx += 256) {
            if (idx < 512) {
                int row = idx >> 3, g = idx & 7;
                cpa16(asb + (row * LDSW + g * 4) * 4,
                      Ap + ((size_t)row * C_ + c) * NE_ + k0 + g * 4);
            } else if (idx < 1152) {
                int j = idx - 512, row = j >> 3, g = j & 7;
                cpa16(wsb + (row * LDSW + g * 4) * 4,
                      Wp + ((size_t)c * NE_ + row) * NE_ + k0 + g * 4);
            } else {
                int j = idx - 1152, row = j / 20, g = j % 20;
                cpa16(weib + (row * LDWEI + g * 4) * 4,
                      W_ei + ((size_t)c * NI_ + row) * NE_ + g * 4);
            }
        }
    } else if (ci == 18 || ci == 21) {
        const bool isB = ci == 18;
        const float* Ap = isB ? l23_fb : r_e;
        const float* Wp = isB ? feedback_proj : W_ee;
        for (int idx = t; idx < 576; idx += 256) {
            if (idx < 256) {
                int row = idx >> 2, g = idx & 3;
                cpa16(asb + (row * LDSW + g * 4) * 4,
                      Ap + ((size_t)row * C_ + c) * NE_ + 64 + g * 4);
            } else {
                int j = idx - 256, row = j >> 2, g = j & 3;
                cpa16(wsb + (row * LDSW + g * 4) * 4,
                      Wp + ((size_t)c * NE_ + row) * NE_ + 64 + g * 4);
            }
        }
    } else {  // ci == 22
        for (int idx = t; idx < 1152; idx += 256) {
            if (idx < 512) {
                int row = idx >> 3, g = idx & 7;
                uint32_t dst = asb + (row * LDSW + g * 4) * 4;
                const float* src = r_i + ((size_t)row * C_ + c) * NI_;
                if (g < 5) cpa16(dst, src + g * 4); else cpa16z(dst, src);
            } else {
                int j = idx - 512, row = j >> 3, g = j & 7;
                uint32_t dst = wsb + (row * LDSW + g * 4) * 4;
                const float* src = W_ie + ((size_t)c * NE_ + row) * NI_;
                if (g < 5) cpa16(dst, src + g * 4); else cpa16z(dst, src);
            }
        }
    }
}

__global__ void __launch_bounds__(256, 2)
ei_bf16(const float* __restrict__ thal, const float* __restrict__ thal_inc,
        const float* __restrict__ l23_fb, const float* __restrict__ r_e,
        const float* __restrict__ r_i, const float* __restrict__ e_v,
        const float* __restrict__ i_v, const float* __restrict__ input_proj,
        const float* __restrict__ feedback_proj, const float* __restrict__ W_ee,
        const float* __restrict__ W_ei, const float* __restrict__ W_ie,
        float* __restrict__ out) {
    extern __shared__ float sm[];
    const int t = threadIdx.x, c = blockIdx.x;
    const int w = t >> 5, lane = t & 31;
    const int wm = w >> 1, wn = w & 1;
    const int m0 = wm * 16, lm = lane >> 2, lc = lane & 3;

    float accE[5][4], accI[3][4];
#pragma unroll
    for (int j = 0; j < 5; j++)
#pragma unroll
        for (int q = 0; q < 4; q++) accE[j][q] = 0.f;
#pragma unroll
    for (int j = 0; j < 3; j++)
#pragma unroll
        for (int q = 0; q < 4; q++) accI[j][q] = 0.f;

    // prime the ring with 3 chunks (prefetch distance = 3)
    prefetch(0, c, t, sm, thal_inc, l23_fb, r_e, r_i,
             input_proj, feedback_proj, W_ee, W_ei, W_ie);
    CP_COMMIT();
    prefetch(1, c, t, sm, thal_inc, l23_fb, r_e, r_i,
             input_proj, feedback_proj, W_ee, W_ei, W_ie);
    CP_COMMIT();
    prefetch(2, c, t, sm, thal_inc, l23_fb, r_e, r_i,
             input_proj, feedback_proj, W_ee, W_ei, W_ie);
    CP_COMMIT();

    const float* Wei = sm + WEI_OFF;
    const bool wiv2 = (lm < 4);   // W_ei row 16+lm valid only for lm<4

    for (int ci = 0; ci < 23; ci++) {
        // groups committed beyond ci: 2 for ci<=20, 1 at ci==21, 0 at ci==22
        if (ci <= 20) CP_WAIT2();
        else if (ci == 21) CP_WAIT1();
        else CP_WAIT0();
        __syncthreads();   // chunk ci visible; slot of ci-1 free for reuse
        if (ci + 3 <= 22) {
            prefetch(ci + 3, c, t, sm, thal_inc, l23_fb, r_e, r_i,
                     input_proj, feedback_proj, W_ee, W_ei, W_ie);
            CP_COMMIT();
        }

        const float* As = sm + (ci % NSTAGE) * STAGE_F;
        const float* Ws = As + A_F;
        const int ksteps = (ci == 18 || ci == 21) ? 1 : 2;
        const bool doI = (ci >= 19 && ci <= 21);
        const bool neg = (ci == 22);
        const int kei0 = (ci - 19) * 32;
        const float2 z = make_float2(0.f, 0.f);

#pragma unroll 2
        for (int ks = 0; ks < ksteps; ks++) {
            const int kb = ks * 16;
            const float* ap = As + (m0 + lm) * LDSW + kb + 2 * lc;
            float2 fa0 = *(const float2*)(ap);
            float2 fa1 = *(const float2*)(ap + 8 * LDSW);
            float2 fa2 = *(const float2*)(ap + 8);
            float2 fa3 = *(const float2*)(ap + 8 * LDSW + 8);
            if (ci < 16) {   // fold broadcast thal (L2-hot) into fragments
                const float* tp = thal + (size_t)(m0 + lm) * E_ + ci * 32 + kb + 2 * lc;
                float2 t00 = __ldg((const float2*)(tp));
                float2 t01 = __ldg((const float2*)(tp + 8));
                float2 t10 = __ldg((const float2*)(tp + 8 * E_));
                float2 t11 = __ldg((const float2*)(tp + 8 * E_ + 8));
                fa0.x += t00.x; fa0.y += t00.y; fa2.x += t01.x; fa2.y += t01.y;
                fa1.x += t10.x; fa1.y += t10.y; fa3.x += t11.x; fa3.y += t11.y;
            }
            if (neg) {
                fa0.x = -fa0.x; fa0.y = -fa0.y; fa1.x = -fa1.x; fa1.y = -fa1.y;
                fa2.x = -fa2.x; fa2.y = -fa2.y; fa3.x = -fa3.x; fa3.y = -fa3.y;
            }
            const uint32_t a0 = bfx2(fa0), a1 = bfx2(fa1), a2 = bfx2(fa2), a3 = bfx2(fa3);
#pragma unroll
            for (int j = 0; j < 5; j++) {
                const float* wp = Ws + (wn * 40 + j * 8 + lm) * LDSW + kb + 2 * lc;
                uint32_t b0 = bfx2(*(const float2*)(wp));
                uint32_t b1 = bfx2(*(const float2*)(wp + 8));
                mma16(accE[j], a0, a1, a2, a3, b0, b1);
            }
            if (doI && wn == 0) {
#pragma unroll
                for (int j = 0; j < 3; j++) {
                    const float* wp = Wei + (j * 8 + lm) * LDWEI + kei0 + kb + 2 * lc;
                    const bool v = (j < 2) || wiv2;
                    uint32_t b0 = bfx2(v ? *(const float2*)(wp) : z);
                    uint32_t b1 = bfx2(v ? *(const float2*)(wp + 8) : z);
                    mma16(accI[j], a0, a1, a2, a3, b0, b1);
                }
            }
        }
    }

    // ---------------- epilogue: leaky integration + relu ----------------
    const int r0 = m0 + lm, r1 = r0 + 8;
#pragma unroll
    for (int j = 0; j < 5; j++) {
        const int col = wn * 40 + j * 8 + 2 * lc;
        const size_t i0 = ((size_t)r0 * C_ + c) * NE_ + col;
        const size_t i1 = ((size_t)r1 * C_ + c) * NE_ + col;
        float2 ev0 = *(const float2*)(e_v + i0);
        float2 ev1 = *(const float2*)(e_v + i1);
        float v0x = ev0.x + DTC * (accE[j][0] - ev0.x);
        float v0y = ev0.y + DTC * (accE[j][1] - ev0.y);
        float v1x = ev1.x + DTC * (accE[j][2] - ev1.x);
        float v1y = ev1.y + DTC * (accE[j][3] - ev1.y);
        *(float2*)(out + i0)          = make_float2(fmaxf(v0x, 0.f), fmaxf(v0y, 0.f));
        *(float2*)(out + i1)          = make_float2(fmaxf(v1x, 0.f), fmaxf(v1y, 0.f));
        *(float2*)(out + OFF_VE + i0) = make_float2(v0x, v0y);
        *(float2*)(out + OFF_VE + i1) = make_float2(v1x, v1y);
    }
    if (wn == 0) {
#pragma unroll
        for (int j = 0; j < 3; j++) {
            const int col = j * 8 + 2 * lc;
            if (col < NI_) {
                const size_t i0 = ((size_t)r0 * C_ + c) * NI_ + col;
                const size_t i1 = ((size_t)r1 * C_ + c) * NI_ + col;
                float2 iv0 = *(const float2*)(i_v + i0);
                float2 iv1 = *(const float2*)(i_v + i1);
                float v0x = iv0.x + DTC * (accI[j][0] - iv0.x);
                float v0y = iv0.y + DTC * (accI[j][1] - iv0.y);
                float v1x = iv1.x + DTC * (accI[j][2] - iv1.x);
                float v1y = iv1.y + DTC * (accI[j][3] - iv1.y);
                *(float2*)(out + OFF_RI + i0) = make_float2(fmaxf(v0x, 0.f), fmaxf(v0y, 0.f));
                *(float2*)(out + OFF_RI + i1) = make_float2(fmaxf(v1x, 0.f), fmaxf(v1y, 0.f));
                *(float2*)(out + OFF_VI + i0) = make_float2(v0x, v0y);
                *(float2*)(out + OFF_VI + i1) = make_float2(v1x, v1y);
            }
        }
    }
}

extern "C" void kernel_launch(void* const* d_in, const int* in_sizes, int n_in,
                              void* d_out, int out_size) {
    (void)in_sizes; (void)n_in; (void)out_size;
    cudaFuncSetAttribute(ei_bf16, cudaFuncAttributeMaxDynamicSharedMemorySize,
                         SMEM_BYTES);
    ei_bf16<<<C_, 256, SMEM_BYTES>>>(
        (const float*)d_in[0],   // thal
        (const float*)d_in[1],   // thal_increments
        (const float*)d_in[2],   // l23_fb
        (const float*)d_in[3],   // r_e
        (const float*)d_in[4],   // r_i
        (const float*)d_in[5],   // e_v
        (const float*)d_in[6],   // i_v
        (const float*)d_in[7],   // input_proj
        (const float*)d_in[8],   // feedback_proj
        (const float*)d_in[9],   // W_ee
        (const float*)d_in[10],  // W_ei
        (const float*)d_in[11],  // W_ie
        (float*)d_out);
}

// round 10
// speedup vs baseline: 2.2471x; 1.2262x over previous
#include <cuda_runtime.h>
#include <cstdint>

constexpr int B_ = 64, C_ = 512, NE_ = 80, NI_ = 20, E_ = 512;
#define DTC 0.1f

// bf16 stage: A [64 x 32] + W [80 x 32], row stride 80 bytes (16B-aligned,
// r*80 mod 128 distinct over 8 rows -> conflict-free ldmatrix).
constexpr int LDB     = 80;                 // bytes per bf16 row
constexpr int A_BYTES = 64 * LDB;           // 5120
constexpr int W_BYTES = 80 * LDB;           // 6400
constexpr int STAGE_B = A_BYTES + W_BYTES;  // 11520
constexpr int NSTAGE  = 3;
// persistent W_ei f32 buffer: 20 rows x 96 floats (cols 80..95 zeroed so the
// ci==21 k-window 64..95 never reads past the row)
constexpr int LDWEI   = 96;
constexpr int WEI_OFF = NSTAGE * STAGE_B;             // 34560 B
constexpr int SMEM_BYTES = WEI_OFF + 20 * LDWEI * 4;  // 42240 B

constexpr size_t OFF_RI = (size_t)B_ * C_ * NE_;
constexpr size_t OFF_VE = OFF_RI + (size_t)B_ * C_ * NI_;
constexpr size_t OFF_VI = OFF_VE + (size_t)B_ * C_ * NE_;

// ---------------- helpers ----------------
__device__ __forceinline__ uint32_t s2u(const void* p) {
    uint32_t a;
    asm("{ .reg .u64 t; cvta.to.shared.u64 t, %1; cvt.u32.u64 %0, t; }" : "=r"(a) : "l"(p));
    return a;
}
__device__ __forceinline__ uint32_t bfx2(float2 f) {
    uint32_t r;
    asm("cvt.rn.bf16x2.f32 %0, %1, %2;" : "=r"(r) : "f"(f.y), "f"(f.x));
    return r;
}
__device__ __forceinline__ void sts_bf(uint32_t addr, float4 v) {
    uint32_t lo = bfx2(make_float2(v.x, v.y));
    uint32_t hi = bfx2(make_float2(v.z, v.w));
    asm volatile("st.shared.v2.b32 [%0], {%1,%2};" :: "r"(addr), "r"(lo), "r"(hi));
}
__device__ __forceinline__ void ldsm4(uint32_t r[4], uint32_t addr) {
    asm volatile("ldmatrix.sync.aligned.m8n8.x4.shared.b16 {%0,%1,%2,%3}, [%4];"
        : "=r"(r[0]), "=r"(r[1]), "=r"(r[2]), "=r"(r[3]) : "r"(addr));
}
__device__ __forceinline__ void mma16(float d[4], uint32_t a0, uint32_t a1,
                                      uint32_t a2, uint32_t a3,
                                      uint32_t b0, uint32_t b1) {
    asm("mma.sync.aligned.m16n8k16.row.col.f32.bf16.bf16.f32 "
        "{%0,%1,%2,%3}, {%4,%5,%6,%7}, {%8,%9}, {%0,%1,%2,%3};"
        : "+f"(d[0]), "+f"(d[1]), "+f"(d[2]), "+f"(d[3])
        : "r"(a0), "r"(a1), "r"(a2), "r"(a3), "r"(b0), "r"(b1));
}

// register-staged chunk: 2 A float4 groups + 3 W float4 groups per thread
struct St { float4 a0, a1, w0, w1, w2; };

// chunk table:
// ci 0-15 : I_ext k0=ci*32 (A=thal_inc, W=input_proj)
// ci 16-18: I_fb  k0=(ci-16)*32 (A=l23_fb, W=feedback_proj; k>=80 zero)
// ci 19-21: I_ee  k0=(ci-19)*32 (A=r_e, W=W_ee; k>=80 zero) + I_ei via Wei
// ci 22   : I_ie  K=20 pad 32 (A=r_i negated at cvt, W=W_ie)
__device__ __forceinline__ void load_chunk(
    int ci, int c, int t, St& s,
    const float* thal_inc, const float* l23_fb, const float* r_e,
    const float* r_i, const float* input_proj, const float* feedback_proj,
    const float* W_ee, const float* W_ie) {
    const int rA = t >> 3, g = t & 7;
    const float4 z = make_float4(0.f, 0.f, 0.f, 0.f);
    if (ci < 16) {
        const int k0 = ci * 32 + g * 4;
        s.a0 = __ldg((const float4*)(thal_inc + ((size_t)rA * C_ + c) * E_ + k0));
        s.a1 = __ldg((const float4*)(thal_inc + ((size_t)(rA + 32) * C_ + c) * E_ + k0));
        s.w0 = __ldg((const float4*)(input_proj + ((size_t)c * NE_ + rA) * E_ + k0));
        s.w1 = __ldg((const float4*)(input_proj + ((size_t)c * NE_ + rA + 32) * E_ + k0));
        s.w2 = (t < 128) ? __ldg((const float4*)(input_proj + ((size_t)c * NE_ + rA + 64) * E_ + k0)) : z;
    } else if (ci < 22) {
        const bool isB = ci < 19;
        const int col = (ci - (isB ? 16 : 19)) * 32 + g * 4;
        const float* Ap = isB ? l23_fb : r_e;
        const float* Wp = isB ? feedback_proj : W_ee;
        const bool v = col < NE_;
        s.a0 = v ? __ldg((const float4*)(Ap + ((size_t)rA * C_ + c) * NE_ + col)) : z;
        s.a1 = v ? __ldg((const float4*)(Ap + ((size_t)(rA + 32) * C_ + c) * NE_ + col)) : z;
        s.w0 = v ? __ldg((const float4*)(Wp + ((size_t)c * NE_ + rA) * NE_ + col)) : z;
        s.w1 = v ? __ldg((const float4*)(Wp + ((size_t)c * NE_ + rA + 32) * NE_ + col)) : z;
        s.w2 = (v && t < 128) ? __ldg((const float4*)(Wp + ((size_t)c * NE_ + rA + 64) * NE_ + col)) : z;
    } else {
        const int col = g * 4;
        const bool v = col < NI_;
        s.a0 = v ? __ldg((const float4*)(r_i + ((size_t)rA * C_ + c) * NI_ + col)) : z;
        s.a1 = v ? __ldg((const float4*)(r_i + ((size_t)(rA + 32) * C_ + c) * NI_ + col)) : z;
        s.w0 = v ? __ldg((const float4*)(W_ie + ((size_t)c * NE_ + rA) * NI_ + col)) : z;
        s.w1 = v ? __ldg((const float4*)(W_ie + ((size_t)c * NE_ + rA + 32) * NI_ + col)) : z;
        s.w2 = (v && t < 128) ? __ldg((const float4*)(W_ie + ((size_t)c * NE_ + rA + 64) * NI_ + col)) : z;
    }
}

__device__ __forceinline__ void cvt_sts(int ci, int t, const St& s,
                                        uint32_t smb, const float* thal) {
    const uint32_t base = smb + (ci % NSTAGE) * STAGE_B;
    const int rA = t >> 3, g = t & 7;
    float4 a0 = s.a0, a1 = s.a1;
    if (ci < 16) {   // fold broadcast thal (L2-hot) before conversion
        const int k0 = ci * 32 + g * 4;
        float4 t0 = __ldg((const float4*)(thal + (size_t)rA * E_ + k0));
        float4 t1 = __ldg((const float4*)(thal + (size_t)(rA + 32) * E_ + k0));
        a0.x += t0.x; a0.y += t0.y; a0.z += t0.z; a0.w += t0.w;
        a1.x += t1.x; a1.y += t1.y; a1.z += t1.z; a1.w += t1.w;
    } else if (ci == 22) {   // negate A for inhibitory current
        a0.x = -a0.x; a0.y = -a0.y; a0.z = -a0.z; a0.w = -a0.w;
        a1.x = -a1.x; a1.y = -a1.y; a1.z = -a1.z; a1.w = -a1.w;
    }
    sts_bf(base + rA * LDB + g * 8, a0);
    sts_bf(base + (rA + 32) * LDB + g * 8, a1);
    const uint32_t wb = base + A_BYTES;
    sts_bf(wb + rA * LDB + g * 8, s.w0);
    sts_bf(wb + (rA + 32) * LDB + g * 8, s.w1);
    if (t < 128) sts_bf(wb + (rA + 64) * LDB + g * 8, s.w2);
}

__global__ void __launch_bounds__(256, 2)
ei_ldsm(const float* __restrict__ thal, const float* __restrict__ thal_inc,
        const float* __restrict__ l23_fb, const float* __restrict__ r_e,
        const float* __restrict__ r_i, const float* __restrict__ e_v,
        const float* __restrict__ i_v, const float* __restrict__ input_proj,
        const float* __restrict__ feedback_proj, const float* __restrict__ W_ee,
        const float* __restrict__ W_ei, const float* __restrict__ W_ie,
        float* __restrict__ out) {
    extern __shared__ char smp[];
    const uint32_t smb = s2u(smp);
    const int t = threadIdx.x, c = blockIdx.x;
    const int w = t >> 5, lane = t & 31;
    const int wm = w >> 1, wn = w & 1;
    const int m0 = wm * 16, lm = lane >> 2, lc = lane & 3;

    float accE[5][4], accI[3][4];
#pragma unroll
    for (int j = 0; j < 5; j++)
#pragma unroll
        for (int q = 0; q < 4; q++) accE[j][q] = 0.f;
#pragma unroll
    for (int j = 0; j < 3; j++)
#pragma unroll
        for (int q = 0; q < 4; q++) accI[j][q] = 0.f;

    // ---- persistent W_ei f32 buffer (20 rows x 96, cols >=80 zero) ----
    for (int idx = t; idx < 480; idx += 256) {
        int row = idx / 24, g = idx % 24;
        float4 v = make_float4(0.f, 0.f, 0.f, 0.f);
        if (g < 20) v = __ldg((const float4*)(W_ei + ((size_t)c * NI_ + row) * NE_ + g * 4));
        *(float4*)(smp + WEI_OFF + (row * LDWEI + g * 4) * 4) = v;
    }
    const float* Wei = (const float*)(smp + WEI_OFF);
    const bool wiv2 = (lm < 4);

    // ---- LDSM/fragment addresses (per lane, slot-relative) ----
    const uint32_t a_off = (uint32_t)((m0 + (lane & 7) + ((lane >> 3) & 1) * 8) * LDB
                                      + (lane >> 4) * 16);
    const uint32_t w_off = (uint32_t)(A_BYTES + (wn * 40 + (lane & 7)) * LDB
                                      + (lane >> 3) * 16);

    // ---- software pipeline: LDG(ci+2) | compute(ci) | cvt+STS(ci+1) ----
    St sA, sB;
    load_chunk(0, c, t, sA, thal_inc, l23_fb, r_e, r_i, input_proj, feedback_proj, W_ee, W_ie);
    load_chunk(1, c, t, sB, thal_inc, l23_fb, r_e, r_i, input_proj, feedback_proj, W_ee, W_ie);
    cvt_sts(0, t, sA, smb, thal);
    __syncthreads();

    auto compute = [&](int ci) {
        const uint32_t base = smb + (ci % NSTAGE) * STAGE_B;
        uint32_t Ak0[4], Ak1[4];
        ldsm4(Ak0, base + a_off);
        ldsm4(Ak1, base + a_off + 32);
#pragma unroll
        for (int j = 0; j < 5; j++) {
            uint32_t Bf[4];
            ldsm4(Bf, base + w_off + (uint32_t)(j * 8 * LDB));
            mma16(accE[j], Ak0[0], Ak0[1], Ak0[2], Ak0[3], Bf[0], Bf[1]);
            mma16(accE[j], Ak1[0], Ak1[1], Ak1[2], Ak1[3], Bf[2], Bf[3]);
        }
        if (ci >= 19 && ci <= 21 && wn == 0) {
            const int kei0 = (ci - 19) * 32;
            const float2 z = make_float2(0.f, 0.f);
#pragma unroll
            for (int j = 0; j < 3; j++) {
                const bool v = (j < 2) || wiv2;
                const float* wp = Wei + (j * 8 + (v ? lm : 0)) * LDWEI + kei0 + 2 * lc;
                uint32_t b0 = bfx2(v ? *(const float2*)(wp) : z);
                uint32_t b1 = bfx2(v ? *(const float2*)(wp + 8) : z);
                mma16(accI[j], Ak0[0], Ak0[1], Ak0[2], Ak0[3], b0, b1);
                uint32_t b2 = bfx2(v ? *(const float2*)(wp + 16) : z);
                uint32_t b3 = bfx2(v ? *(const float2*)(wp + 24) : z);
                mma16(accI[j], Ak1[0], Ak1[1], Ak1[2], Ak1[3], b2, b3);
            }
        }
    };

#pragma unroll 1
    for (int ci = 0; ci < 23; ci += 2) {
        if (ci + 2 < 23)
            load_chunk(ci + 2, c, t, sA, thal_inc, l23_fb, r_e, r_i,
                       input_proj, feedback_proj, W_ee, W_ie);
        compute(ci);
        if (ci + 1 < 23) cvt_sts(ci + 1, t, sB, smb, thal);
        __syncthreads();
        if (ci + 1 < 23) {
            if (ci + 3 < 23)
                load_chunk(ci + 3, c, t, sB, thal_inc, l23_fb, r_e, r_i,
                           input_proj, feedback_proj, W_ee, W_ie);
            compute(ci + 1);
            if (ci + 2 < 23) cvt_sts(ci + 2, t, sA, smb, thal);
            __syncthreads();
        }
    }

    // ---------------- epilogue: leaky integration + relu ----------------
    const int r0 = m0 + lm, r1 = r0 + 8;
#pragma unroll
    for (int j = 0; j < 5; j++) {
        const int col = wn * 40 + j * 8 + 2 * lc;
        const size_t i0 = ((size_t)r0 * C_ + c) * NE_ + col;
        const size_t i1 = ((size_t)r1 * C_ + c) * NE_ + col;
        float2 ev0 = *(const float2*)(e_v + i0);
        float2 ev1 = *(const float2*)(e_v + i1);
        float v0x = ev0.x + DTC * (accE[j][0] - ev0.x);
        float v0y = ev0.y + DTC * (accE[j][1] - ev0.y);
        float v1x = ev1.x + DTC * (accE[j][2] - ev1.x);
        float v1y = ev1.y + DTC * (accE[j][3] - ev1.y);
        *(float2*)(out + i0)          = make_float2(fmaxf(v0x, 0.f), fmaxf(v0y, 0.f));
        *(float2*)(out + i1)          = make_float2(fmaxf(v1x, 0.f), fmaxf(v1y, 0.f));
        *(float2*)(out + OFF_VE + i0) = make_float2(v0x, v0y);
        *(float2*)(out + OFF_VE + i1) = make_float2(v1x, v1y);
    }
    if (wn == 0) {
#pragma unroll
        for (int j = 0; j < 3; j++) {
            const int col = j * 8 + 2 * lc;
            if (col < NI_) {
                const size_t i0 = ((size_t)r0 * C_ + c) * NI_ + col;
                const size_t i1 = ((size_t)r1 * C_ + c) * NI_ + col;
                float2 iv0 = *(const float2*)(i_v + i0);
                float2 iv1 = *(const float2*)(i_v + i1);
                float v0x = iv0.x + DTC * (accI[j][0] - iv0.x);
                float v0y = iv0.y + DTC * (accI[j][1] - iv0.y);
                float v1x = iv1.x + DTC * (accI[j][2] - iv1.x);
                float v1y = iv1.y + DTC * (accI[j][3] - iv1.y);
                *(float2*)(out + OFF_RI + i0) = make_float2(fmaxf(v0x, 0.f), fmaxf(v0y, 0.f));
                *(float2*)(out + OFF_RI + i1) = make_float2(fmaxf(v1x, 0.f), fmaxf(v1y, 0.f));
                *(float2*)(out + OFF_VI + i0) = make_float2(v0x, v0y);
                *(float2*)(out + OFF_VI + i1) = make_float2(v1x, v1y);
            }
        }
    }
}

extern "C" void kernel_launch(void* const* d_in, const int* in_sizes, int n_in,
                              void* d_out, int out_size) {
    (void)in_sizes; (void)n_in; (void)out_size;
    cudaFuncSetAttribute(ei_ldsm, cudaFuncAttributeMaxDynamicSharedMemorySize,
                         SMEM_BYTES);
    ei_ldsm<<<C_, 256, SMEM_BYTES>>>(
        (const float*)d_in[0],   // thal
        (const float*)d_in[1],   // thal_increments
        (const float*)d_in[2],   // l23_fb
        (const float*)d_in[3],   // r_e
        (const float*)d_in[4],   // r_i
        (const float*)d_in[5],   // e_v
        (const float*)d_in[6],   // i_v
        (const float*)d_in[7],   // input_proj
        (const float*)d_in[8],   // feedback_proj
        (const float*)d_in[9],   // W_ee
        (const float*)d_in[10],  // W_ei
        (const float*)d_in[11],  // W_ie
        (float*)d_out);
}